// round 2
// baseline (speedup 1.0000x reference)
#include <cuda_runtime.h>
#include <cstdint>

#define BB 8
#define CC 256
#define HH 160
#define WW 160
#define HW (HH*WW)          // 25600
#define TH 16
#define TW 32

// ---- scratch (no allocations allowed) ----
__device__ float g_c_sum[BB*CC];          // per-(b,c) sum of g over H,W
__device__ float g_w_gate[BB*CC];         // channel gate
__device__ float g_s_in[BB*4*HW];         // [B,4,H,W] descriptor
__device__ float g_s_map[BB*HW];          // spatial gate
__device__ float g_ab[2];                 // softplus(alpha), softplus(beta)

__global__ void zero_kernel() {
    int i = blockIdx.x * 256 + threadIdx.x;
    if (i < BB*CC) g_c_sum[i] = 0.f;
}

// ---------------------------------------------------------------------------
// Kernel 1: Sobel magnitude + all reductions.
// grid (W/TW, H/TH, B), block 256. Each block loops over all 256 channels.
// Separable Sobel: vsmooth=[1,2,1], vdiff=[1,0,-1];
//   gx = 0.25*(vs[c-1]-vs[c+1]),  gy = 0.25*(vd[c-1]+2*vd[c]+vd[c+1])
// ---------------------------------------------------------------------------
__global__ __launch_bounds__(256) void k_edge(const float* __restrict__ x) {
    __shared__ float xs[(TH+2)*(TW+2)];   // 18*34 = 612
    __shared__ float cpart[CC];

    const int tid  = threadIdx.x;
    const int lane = tid & 31;
    const int tx0  = blockIdx.x * TW;
    const int ty0  = blockIdx.y * TH;
    const int b    = blockIdx.z;

    for (int i = tid; i < CC; i += 256) cpart[i] = 0.f;

    // channel-invariant load offsets (3 fragments per thread for 612 elems)
    int ld_goff[3], ld_soff[3];
    #pragma unroll
    for (int k = 0; k < 3; k++) {
        int i  = tid + k * 256;
        int r  = i / 34, cc2 = i % 34;
        int gy = ty0 - 1 + r, gx = tx0 - 1 + cc2;
        bool in_tile = (i < 612);
        bool ok = in_tile && ((unsigned)gy < HH) && ((unsigned)gx < WW);
        ld_goff[k] = ok ? (gy * WW + gx) : -1;
        ld_soff[k] = in_tile ? i : -1;
    }

    const int pc    = lane;
    const int pr0   = (tid >> 5) * 2;       // 2 vertically adjacent pixels/thread
    const int sbase = pr0 * 34 + pc;        // xs[pr0][pc]

    float sumx0 = 0.f, sumx1 = 0.f, sumg0 = 0.f, sumg1 = 0.f;
    float maxx0 = -3.4e38f, maxx1 = -3.4e38f, maxg0 = 0.f, maxg1 = 0.f;
    float x0c = 0.f, x1c = 0.f;

    const float* xc = x + (size_t)b * CC * HW;
    for (int c = 0; c < CC; c++, xc += HW) {
        #pragma unroll
        for (int k = 0; k < 3; k++) {
            if (ld_soff[k] >= 0)
                xs[ld_soff[k]] = (ld_goff[k] >= 0) ? xc[ld_goff[k]] : 0.f;
        }
        __syncthreads();

        float s0[3], d0[3], s1[3], d1[3];
        #pragma unroll
        for (int j = 0; j < 3; j++) {
            float a0 = xs[sbase + j];
            float a1 = xs[sbase + 34 + j];
            float a2 = xs[sbase + 68 + j];
            float a3 = xs[sbase + 102 + j];
            s0[j] = fmaf(2.f, a1, a0) + a2;
            d0[j] = a0 - a2;
            s1[j] = fmaf(2.f, a2, a1) + a3;
            d1[j] = a1 - a3;
            if (j == 1) { x0c = a1; x1c = a2; }
        }
        float gx0 = 0.25f * (s0[0] - s0[2]);
        float gy0 = 0.25f * (fmaf(2.f, d0[1], d0[0]) + d0[2]);
        float g0  = sqrtf(fmaf(gy0, gy0, fmaf(gx0, gx0, 1e-12f)));
        float gx1 = 0.25f * (s1[0] - s1[2]);
        float gy1 = 0.25f * (fmaf(2.f, d1[1], d1[0]) + d1[2]);
        float g1  = sqrtf(fmaf(gy1, gy1, fmaf(gx1, gx1, 1e-12f)));

        sumx0 += x0c; maxx0 = fmaxf(maxx0, x0c);
        sumx1 += x1c; maxx1 = fmaxf(maxx1, x1c);
        sumg0 += g0;  maxg0 = fmaxf(maxg0, g0);
        sumg1 += g1;  maxg1 = fmaxf(maxg1, g1);

        float part = g0 + g1;
        #pragma unroll
        for (int off = 16; off; off >>= 1)
            part += __shfl_down_sync(0xffffffffu, part, off);
        if (lane == 0) atomicAdd(&cpart[c], part);
        __syncthreads();
    }
    __syncthreads();

    const float invC = 1.f / CC;
    int py = ty0 + pr0, px = tx0 + pc;
    float* s_in = g_s_in + (size_t)b * 4 * HW;
    int p0 = py * WW + px, p1 = p0 + WW;
    s_in[p0]          = sumx0 * invC;   s_in[p1]          = sumx1 * invC;
    s_in[HW + p0]     = maxx0;          s_in[HW + p1]     = maxx1;
    s_in[2*HW + p0]   = sumg0 * invC;   s_in[2*HW + p1]   = sumg1 * invC;
    s_in[3*HW + p0]   = maxg0;          s_in[3*HW + p1]   = maxg1;

    atomicAdd(&g_c_sum[b*CC + tid], cpart[tid]);
}

// ---------------------------------------------------------------------------
// Kernel 2: channel MLP gate (tiny). grid = B, block = 256.
// ---------------------------------------------------------------------------
__global__ void k_mlp(const float* __restrict__ w1, const float* __restrict__ w2,
                      const float* __restrict__ alpha, const float* __restrict__ beta) {
    __shared__ float cv[CC];
    __shared__ float h[16];
    int b = blockIdx.x, t = threadIdx.x;
    cv[t] = g_c_sum[b*CC + t] * (1.f / HW);
    __syncthreads();
    if (t < 16) {
        float acc = 0.f;
        for (int c2 = 0; c2 < CC; c2++) acc = fmaf(cv[c2], w1[t*CC + c2], acc);
        h[t] = fmaxf(acc, 0.f);
    }
    __syncthreads();
    float acc = 0.f;
    #pragma unroll
    for (int j = 0; j < 16; j++) acc = fmaf(h[j], w2[t*16 + j], acc);
    g_w_gate[b*CC + t] = 1.f / (1.f + __expf(-acc));
    if (b == 0 && t == 0) {
        float av = alpha[0], bv = beta[0];
        g_ab[0] = (av > 20.f) ? av : log1pf(expf(av));
        g_ab[1] = (bv > 20.f) ? bv : log1pf(expf(bv));
    }
}

// ---------------------------------------------------------------------------
// Kernel 3: 7x7x4 conv + sigmoid -> s map. grid (W/TW, H/TH, B), block 256.
// ---------------------------------------------------------------------------
__global__ __launch_bounds__(256) void k_spatial(const float* __restrict__ sw,
                                                 const float* __restrict__ sb) {
    __shared__ float t[4*22*38];          // halo tile, 3344 floats
    __shared__ float wsm[196];
    int tid = threadIdx.x;
    int tx0 = blockIdx.x * TW, ty0 = blockIdx.y * TH, b = blockIdx.z;
    if (tid < 196) wsm[tid] = sw[tid];
    const float* s_in = g_s_in + (size_t)b * 4 * HW;
    for (int i = tid; i < 4*22*38; i += 256) {
        int ch  = i / (22*38);
        int rem = i - ch * (22*38);
        int r   = rem / 38, cc2 = rem - r * 38;
        int gy  = ty0 - 3 + r, gx = tx0 - 3 + cc2;
        float v = 0.f;
        if ((unsigned)gy < HH && (unsigned)gx < WW) v = s_in[ch*HW + gy*WW + gx];
        t[i] = v;
    }
    __syncthreads();

    int pc  = tid & 31;
    int pr0 = (tid >> 5) * 2;
    float bias = sb[0];
    #pragma unroll
    for (int p = 0; p < 2; p++) {
        int pr = pr0 + p;
        float acc = bias;
        #pragma unroll
        for (int ch = 0; ch < 4; ch++) {
            #pragma unroll
            for (int u = 0; u < 7; u++) {
                const float* row = &t[ch*(22*38) + (pr+u)*38 + pc];
                const float* wr  = &wsm[ch*49 + u*7];
                #pragma unroll
                for (int v = 0; v < 7; v++) acc = fmaf(row[v], wr[v], acc);
            }
        }
        g_s_map[b*HW + (ty0+pr)*WW + tx0 + pc] = 1.f / (1.f + __expf(-acc));
    }
}

// ---------------------------------------------------------------------------
// Kernel 4: streaming apply. out = x * (1 + a*s) * (1 + b*w). float4.
// ---------------------------------------------------------------------------
__global__ __launch_bounds__(256) void k_apply(const float* __restrict__ x,
                                               float* __restrict__ out) {
    const float a  = g_ab[0];
    const float bb = g_ab[1];
    const int hw4  = HW / 4;             // 6400
    const int chw4 = CC * hw4;           // 1638400
    int i4 = blockIdx.x * 256 + threadIdx.x;   // < 13,107,200
    int b  = i4 / chw4;
    int r  = i4 - b * chw4;
    int c  = r / hw4;
    int p4 = r - c * hw4;
    float wg = fmaf(bb, g_w_gate[b*CC + c], 1.f);
    float4 s4 = ((const float4*)g_s_map)[b*hw4 + p4];
    float4 x4 = ((const float4*)x)[i4];
    float4 o;
    o.x = x4.x * fmaf(a, s4.x, 1.f) * wg;
    o.y = x4.y * fmaf(a, s4.y, 1.f) * wg;
    o.z = x4.z * fmaf(a, s4.z, 1.f) * wg;
    o.w = x4.w * fmaf(a, s4.w, 1.f) * wg;
    ((float4*)out)[i4] = o;
}

// ---------------------------------------------------------------------------
extern "C" void kernel_launch(void* const* d_in, const int* in_sizes, int n_in,
                              void* d_out, int out_size) {
    const float* x  = (const float*)d_in[0];
    const float* w1 = (const float*)d_in[1];
    const float* w2 = (const float*)d_in[2];
    const float* sw = (const float*)d_in[3];
    const float* sb = (const float*)d_in[4];
    const float* al = (const float*)d_in[5];
    const float* be = (const float*)d_in[6];
    float* out = (float*)d_out;

    zero_kernel<<<(BB*CC + 255)/256, 256>>>();
    dim3 g1(WW/TW, HH/TH, BB);
    k_edge<<<g1, 256>>>(x);
    k_mlp<<<BB, 256>>>(w1, w2, al, be);
    k_spatial<<<g1, 256>>>(sw, sb);
    int total4 = BB * CC * HW / 4;
    k_apply<<<(total4 + 255)/256, 256>>>(x, out);
}

// round 4
// speedup vs baseline: 2.1742x; 2.1742x over previous
#include <cuda_runtime.h>
#include <cstdint>

#define BB 8
#define CC 256
#define HH 160
#define WW 160
#define HW (HH*WW)          // 25600
#define TH 16
#define TW 32
#define NG 8                // channel groups
#define CPG 32              // channels per group
#define NCI 4               // channels per smem iteration

// ---- scratch (no allocations allowed) ----
__device__ float    g_c_sum[BB*CC];       // per-(b,c) sum of g
__device__ float    g_w_gate[BB*CC];      // channel gate
__device__ float    g_sum_x[BB*HW];       // per-pixel sum over channels of x
__device__ float    g_sum_g[BB*HW];       // per-pixel sum over channels of g
__device__ unsigned g_max_x[BB*HW];       // ordered-uint max of x
__device__ unsigned g_max_g[BB*HW];       // ordered-uint max of g
__device__ float    g_s_map[BB*HW];       // spatial gate
__device__ float    g_ab[2];              // softplus(alpha), softplus(beta)

// monotone float<->uint order map
__device__ __forceinline__ unsigned omap(float f) {
    unsigned u = __float_as_uint(f);
    return (u & 0x80000000u) ? ~u : (u | 0x80000000u);
}
__device__ __forceinline__ float ounmap(unsigned u) {
    return __uint_as_float((u & 0x80000000u) ? (u ^ 0x80000000u) : ~u);
}

__global__ void zero_kernel() {
    int i = blockIdx.x * 256 + threadIdx.x;
    if (i < BB*HW) {
        g_sum_x[i] = 0.f; g_sum_g[i] = 0.f;
        g_max_x[i] = 0u;  g_max_g[i] = 0u;   // u=0 is below every mapped float
    }
    if (i < BB*CC) g_c_sum[i] = 0.f;
}

// ---------------------------------------------------------------------------
// Kernel 1: Sobel magnitude + reductions. Channel-split 8 ways.
// grid (W/TW, H/TH, B*NG), block 256; 2 vertical px/thread; 4 channels/iter.
// ---------------------------------------------------------------------------
__global__ __launch_bounds__(256) void k_edge(const float* __restrict__ x) {
    __shared__ float xs[NCI*612];        // 4 x (18*34)
    __shared__ float cpartg[CPG];

    const int tid  = threadIdx.x;
    const int lane = tid & 31;
    const int tx0  = blockIdx.x * TW;
    const int ty0  = blockIdx.y * TH;
    const int bz   = blockIdx.z;
    const int b    = bz / NG;
    const int cbase = (bz % NG) * CPG;

    if (tid < CPG) cpartg[tid] = 0.f;

    // channel-invariant fragment offsets: 2448 elems, 10 frags (last partial)
    int ld_goff[10];
    #pragma unroll
    for (int k = 0; k < 10; k++) {
        int i   = tid + k * 256;
        int ch  = i / 612;
        int rem = i - ch * 612;
        int r   = rem / 34, cc2 = rem - r * 34;
        int gy  = ty0 - 1 + r, gx = tx0 - 1 + cc2;
        bool ok = ((unsigned)gy < HH) && ((unsigned)gx < WW);
        ld_goff[k] = ok ? (ch * HW + gy * WW + gx) : -1;
    }

    const int pc    = lane;
    const int pr0   = (tid >> 5) * 2;
    const int sbase = pr0 * 34 + pc;

    float sumx0 = 0.f, sumx1 = 0.f, sumg0 = 0.f, sumg1 = 0.f;
    float maxx0 = -3.4e38f, maxx1 = -3.4e38f, maxg0 = 0.f, maxg1 = 0.f;

    const float* xg = x + ((size_t)b * CC + cbase) * HW;
    for (int c0 = 0; c0 < CPG; c0 += NCI) {
        const float* base = xg + (size_t)c0 * HW;
        #pragma unroll
        for (int k = 0; k < 9; k++)
            xs[tid + k*256] = (ld_goff[k] >= 0) ? base[ld_goff[k]] : 0.f;
        if (tid < 2448 - 9*256)
            xs[tid + 9*256] = (ld_goff[9] >= 0) ? base[ld_goff[9]] : 0.f;
        __syncthreads();

        float part[NCI];
        #pragma unroll
        for (int ci = 0; ci < NCI; ci++) {
            const float* xsp = xs + ci * 612;
            float s0[3], d0[3], s1[3], d1[3];
            float x0c = 0.f, x1c = 0.f;
            #pragma unroll
            for (int j = 0; j < 3; j++) {
                float a0 = xsp[sbase + j];
                float a1 = xsp[sbase + 34 + j];
                float a2 = xsp[sbase + 68 + j];
                float a3 = xsp[sbase + 102 + j];
                s0[j] = fmaf(2.f, a1, a0) + a2;
                d0[j] = a0 - a2;
                s1[j] = fmaf(2.f, a2, a1) + a3;
                d1[j] = a1 - a3;
                if (j == 1) { x0c = a1; x1c = a2; }
            }
            float gx0 = 0.25f * (s0[0] - s0[2]);
            float gy0 = 0.25f * (fmaf(2.f, d0[1], d0[0]) + d0[2]);
            float g0  = sqrtf(fmaf(gy0, gy0, fmaf(gx0, gx0, 1e-12f)));
            float gx1 = 0.25f * (s1[0] - s1[2]);
            float gy1 = 0.25f * (fmaf(2.f, d1[1], d1[0]) + d1[2]);
            float g1  = sqrtf(fmaf(gy1, gy1, fmaf(gx1, gx1, 1e-12f)));

            sumx0 += x0c; maxx0 = fmaxf(maxx0, x0c);
            sumx1 += x1c; maxx1 = fmaxf(maxx1, x1c);
            sumg0 += g0;  maxg0 = fmaxf(maxg0, g0);
            sumg1 += g1;  maxg1 = fmaxf(maxg1, g1);
            part[ci] = g0 + g1;
        }
        // 4 independent reduction chains (ILP hides shfl latency)
        #pragma unroll
        for (int off = 16; off; off >>= 1) {
            #pragma unroll
            for (int ci = 0; ci < NCI; ci++)
                part[ci] += __shfl_down_sync(0xffffffffu, part[ci], off);
        }
        if (lane == 0) {
            #pragma unroll
            for (int ci = 0; ci < NCI; ci++)
                atomicAdd(&cpartg[c0 + ci], part[ci]);
        }
        __syncthreads();
    }

    // per-pixel partial combine across channel groups
    int p0 = b * HW + (ty0 + pr0) * WW + tx0 + pc;
    int p1 = p0 + WW;
    atomicAdd(&g_sum_x[p0], sumx0);  atomicAdd(&g_sum_x[p1], sumx1);
    atomicAdd(&g_sum_g[p0], sumg0);  atomicAdd(&g_sum_g[p1], sumg1);
    atomicMax(&g_max_x[p0], omap(maxx0));  atomicMax(&g_max_x[p1], omap(maxx1));
    atomicMax(&g_max_g[p0], omap(maxg0));  atomicMax(&g_max_g[p1], omap(maxg1));

    if (tid < CPG) atomicAdd(&g_c_sum[b*CC + cbase + tid], cpartg[tid]);
}

// ---------------------------------------------------------------------------
// Kernel 2: channel MLP gate (tiny). grid = B, block = 256.
// ---------------------------------------------------------------------------
__global__ void k_mlp(const float* __restrict__ w1, const float* __restrict__ w2,
                      const float* __restrict__ alpha, const float* __restrict__ beta) {
    __shared__ float cv[CC];
    __shared__ float h[16];
    int b = blockIdx.x, t = threadIdx.x;
    cv[t] = g_c_sum[b*CC + t] * (1.f / HW);
    __syncthreads();
    if (t < 16) {
        float acc = 0.f;
        for (int c2 = 0; c2 < CC; c2++) acc = fmaf(cv[c2], w1[t*CC + c2], acc);
        h[t] = fmaxf(acc, 0.f);
    }
    __syncthreads();
    float acc = 0.f;
    #pragma unroll
    for (int j = 0; j < 16; j++) acc = fmaf(h[j], w2[t*16 + j], acc);
    g_w_gate[b*CC + t] = 1.f / (1.f + __expf(-acc));
    if (b == 0 && t == 0) {
        float av = alpha[0], bv = beta[0];
        g_ab[0] = (av > 20.f) ? av : log1pf(expf(av));
        g_ab[1] = (bv > 20.f) ? bv : log1pf(expf(bv));
    }
}

// ---------------------------------------------------------------------------
// Kernel 3: 7x7x4 conv + sigmoid. Tile 32x32, 4 px/thread, row reuse.
// grid (5, 5, B), block 256.
// ---------------------------------------------------------------------------
#define STH 32
#define STW 32
__global__ __launch_bounds__(256, 3) void k_spatial(const float* __restrict__ sw,
                                                    const float* __restrict__ sb) {
    __shared__ float t[4*38*38];          // 23104 B
    __shared__ float wsm[196];
    const int tid = threadIdx.x;
    const int tx0 = blockIdx.x * STW, ty0 = blockIdx.y * STH, b = blockIdx.z;
    if (tid < 196) wsm[tid] = sw[tid];

    const int pbase = b * HW;
    const float invC = 1.f / CC;
    for (int i = tid; i < 4*38*38; i += 256) {
        int ch  = i / 1444;
        int rem = i - ch * 1444;
        int r   = rem / 38, cc2 = rem - r * 38;
        int gy  = ty0 - 3 + r, gx = tx0 - 3 + cc2;
        float v = 0.f;
        if ((unsigned)gy < HH && (unsigned)gx < WW) {
            int p = pbase + gy * WW + gx;
            if      (ch == 0) v = g_sum_x[p] * invC;
            else if (ch == 1) v = ounmap(g_max_x[p]);
            else if (ch == 2) v = g_sum_g[p] * invC;
            else              v = ounmap(g_max_g[p]);
        }
        t[i] = v;
    }
    __syncthreads();

    const int pc  = tid & 31;
    const int pr0 = (tid >> 5) * 4;       // 4 vertical px/thread
    float bias = sb[0];
    float acc[4] = {bias, bias, bias, bias};

    #pragma unroll
    for (int ch = 0; ch < 4; ch++) {
        #pragma unroll
        for (int u = 0; u < 10; u++) {    // rows pr0+u, shared by outputs
            float row[7];
            const float* rp = &t[ch*1444 + (pr0 + u)*38 + pc];
            #pragma unroll
            for (int v = 0; v < 7; v++) row[v] = rp[v];
            #pragma unroll
            for (int p = 0; p < 4; p++) {
                int ky = u - p;
                if (ky >= 0 && ky < 7) {
                    const float* wr = &wsm[ch*49 + ky*7];
                    #pragma unroll
                    for (int v = 0; v < 7; v++)
                        acc[p] = fmaf(row[v], wr[v], acc[p]);
                }
            }
        }
    }
    #pragma unroll
    for (int p = 0; p < 4; p++)
        g_s_map[pbase + (ty0 + pr0 + p)*WW + tx0 + pc] = 1.f / (1.f + __expf(-acc[p]));
}

// ---------------------------------------------------------------------------
// Kernel 4: streaming apply. out = x * (1 + a*s) * (1 + b*w). float4.
// ---------------------------------------------------------------------------
__global__ __launch_bounds__(256) void k_apply(const float* __restrict__ x,
                                               float* __restrict__ out) {
    const float a  = g_ab[0];
    const float bb = g_ab[1];
    const int hw4  = HW / 4;             // 6400
    const int chw4 = CC * hw4;           // 1638400
    int i4 = blockIdx.x * 256 + threadIdx.x;
    int b  = i4 / chw4;
    int r  = i4 - b * chw4;
    int c  = r / hw4;
    int p4 = r - c * hw4;
    float wg = fmaf(bb, g_w_gate[b*CC + c], 1.f);
    float4 s4 = ((const float4*)g_s_map)[b*hw4 + p4];
    float4 x4 = ((const float4*)x)[i4];
    float4 o;
    o.x = x4.x * fmaf(a, s4.x, 1.f) * wg;
    o.y = x4.y * fmaf(a, s4.y, 1.f) * wg;
    o.z = x4.z * fmaf(a, s4.z, 1.f) * wg;
    o.w = x4.w * fmaf(a, s4.w, 1.f) * wg;
    ((float4*)out)[i4] = o;
}

// ---------------------------------------------------------------------------
extern "C" void kernel_launch(void* const* d_in, const int* in_sizes, int n_in,
                              void* d_out, int out_size) {
    const float* x  = (const float*)d_in[0];
    const float* w1 = (const float*)d_in[1];
    const float* w2 = (const float*)d_in[2];
    const float* sw = (const float*)d_in[3];
    const float* sb = (const float*)d_in[4];
    const float* al = (const float*)d_in[5];
    const float* be = (const float*)d_in[6];
    float* out = (float*)d_out;

    zero_kernel<<<(BB*HW + 255)/256, 256>>>();
    dim3 g1(WW/TW, HH/TH, BB*NG);
    k_edge<<<g1, 256>>>(x);
    k_mlp<<<BB, 256>>>(w1, w2, al, be);
    dim3 g3(WW/STW, HH/STH, BB);
    k_spatial<<<g3, 256>>>(sw, sb);
    int total4 = BB * CC * HW / 4;
    k_apply<<<(total4 + 255)/256, 256>>>(x, out);
}